// round 13
// baseline (speedup 1.0000x reference)
#include <cuda_runtime.h>
#include <cuda_fp16.h>
#include <cstdint>
#include <cstddef>

// y[32,11008] = x[32,4096] @ (Wq * scale)^T + bias
// R13: R12 main (barrier-free fp16 HMMA, NSPLIT=16) + fused deterministic
// last-finisher reduce (per-mtile counter; fixed split-order sum; L2-fresh
// partials; overlapped with compute; single kernel launch).

#define OUTN 11008
#define INK  4096
#define TM   128
#define NSPLIT 16
#define CHUNKS 4                    // K-chunks per CTA (64 k each), K=256/CTA
#define NMTILE (OUTN / TM)          // 86
#define NCTA (NMTILE * NSPLIT)      // 1376
#define NTHREADS 256
#define XROW 544                    // x smem row stride bytes (136w = 8 mod 32)

__device__ __align__(16) float g_part[NSPLIT * 32 * OUTN];   // 22.5 MB partials
__device__ int g_cnt[NMTILE];                                 // zero-init; reset by finisher

// ternary int32 pair -> packed fp16x2 {0,+-1.0}; 4 lat-4 ALU ops.
__device__ __forceinline__ uint32_t tern2h(uint32_t w0, uint32_t w1) {
    uint32_t p = __byte_perm(w0, w1, 0x5410);
    uint32_t m = (p & 0x00010001u) * 0x3C00u;
    return m | (p & 0x80008000u);
}

__device__ __forceinline__ void mma16816(float d[4],
                                         uint32_t a0, uint32_t a1, uint32_t a2, uint32_t a3,
                                         uint32_t b0, uint32_t b1) {
    asm volatile(
        "mma.sync.aligned.m16n8k16.row.col.f32.f16.f16.f32 "
        "{%0,%1,%2,%3}, {%4,%5,%6,%7}, {%8,%9}, {%0,%1,%2,%3};\n"
        : "+f"(d[0]), "+f"(d[1]), "+f"(d[2]), "+f"(d[3])
        : "r"(a0), "r"(a1), "r"(a2), "r"(a3), "r"(b0), "r"(b1));
}

__global__ void __launch_bounds__(NTHREADS, 2)
lin2b_main(const float* __restrict__ X, const int* __restrict__ W,
           const float* __restrict__ SC, const float* __restrict__ BI,
           float* __restrict__ OUT)
{
    __shared__ __align__(16) unsigned char xsm[32 * XROW];   // 17 KB
    __shared__ int s_last;

    int tid  = threadIdx.x;
    int wid  = tid >> 5;
    int lane = tid & 31;
    int rr   = lane >> 2;
    int cc   = lane & 3;

    int mtile = blockIdx.x >> 4;
    int split = blockIdx.x & 15;
    int row0  = mtile * TM;
    int k0    = split * (CHUNKS * 64);

    // ---- prologue: convert this CTA's x slice (32 x 256) f32 -> fp16 smem ---
    {
        int xr  = tid >> 3;
        int kb  = (tid & 7) * 32;
        const float* xs = X + (size_t)xr * INK + k0 + kb;
        unsigned char* xd = xsm + xr * XROW + kb * 2;
#pragma unroll
        for (int g = 0; g < 2; ++g) {
            uint4 st[2];
#pragma unroll
            for (int q = 0; q < 2; ++q) {
                float4 v0 = *reinterpret_cast<const float4*>(xs + g * 16 + q * 8);
                float4 v1 = *reinterpret_cast<const float4*>(xs + g * 16 + q * 8 + 4);
                __half2 p0 = __floats2half2_rn(v0.x, v0.y);
                __half2 p1 = __floats2half2_rn(v0.z, v0.w);
                __half2 p2 = __floats2half2_rn(v1.x, v1.y);
                __half2 p3 = __floats2half2_rn(v1.z, v1.w);
                st[q].x = *reinterpret_cast<uint32_t*>(&p0);
                st[q].y = *reinterpret_cast<uint32_t*>(&p1);
                st[q].z = *reinterpret_cast<uint32_t*>(&p2);
                st[q].w = *reinterpret_cast<uint32_t*>(&p3);
            }
            *reinterpret_cast<uint4*>(xd + g * 32)      = st[0];
            *reinterpret_cast<uint4*>(xd + g * 32 + 16) = st[1];
        }
    }

    const int* wp0 = W + (size_t)(row0 + wid * 16 + rr) * INK + k0 + 4 * cc;
    const int* wp1 = wp0 + (size_t)8 * INK;

    float acc[4][4];
#pragma unroll
    for (int i = 0; i < 4; ++i)
#pragma unroll
        for (int j = 0; j < 4; ++j) acc[i][j] = 0.0f;

    uint4 w0[8], w1[8];
#pragma unroll
    for (int s = 0; s < 4; ++s) {
        w0[2*s]   = *reinterpret_cast<const uint4*>(wp0 + s * 16);
        w0[2*s+1] = *reinterpret_cast<const uint4*>(wp1 + s * 16);
    }
    __syncthreads();    // x smem ready; read-only afterwards

    const unsigned char* xb = xsm + rr * XROW + cc * 8;

#pragma unroll
    for (int c = 0; c < CHUNKS; ++c) {
        uint4* wcur = (c & 1) ? w1 : w0;
        uint4* wnxt = (c & 1) ? w0 : w1;
        if (c + 1 < CHUNKS) {
#pragma unroll
            for (int s = 0; s < 4; ++s) {
                wnxt[2*s]   = *reinterpret_cast<const uint4*>(wp0 + (c + 1) * 64 + s * 16);
                wnxt[2*s+1] = *reinterpret_cast<const uint4*>(wp1 + (c + 1) * 64 + s * 16);
            }
        }
#pragma unroll
        for (int s = 0; s < 4; ++s) {
            uint4 wa = wcur[2*s];
            uint4 wb = wcur[2*s+1];
            uint32_t a0 = tern2h(wa.x, wa.y);
            uint32_t a2 = tern2h(wa.z, wa.w);
            uint32_t a1 = tern2h(wb.x, wb.y);
            uint32_t a3 = tern2h(wb.z, wb.w);
#pragma unroll
            for (int nf = 0; nf < 4; ++nf) {
                uint2 bv = *reinterpret_cast<const uint2*>(
                    xb + nf * (8 * XROW) + c * 128 + s * 32);
                mma16816(acc[nf], a0, a1, a2, a3, bv.x, bv.y);
            }
        }
    }

    // ---- partial store ----
    int o0 = row0 + wid * 16 + rr;
    int o1 = o0 + 8;
    float* pb = g_part + (size_t)split * 32 * OUTN;
#pragma unroll
    for (int nf = 0; nf < 4; ++nf) {
        int b0 = nf * 8 + 2 * cc;
        int b1 = b0 + 1;
        pb[(size_t)b0 * OUTN + o0] = acc[nf][0];
        pb[(size_t)b1 * OUTN + o0] = acc[nf][1];
        pb[(size_t)b0 * OUTN + o1] = acc[nf][2];
        pb[(size_t)b1 * OUTN + o1] = acc[nf][3];
    }

    // ---- last-finisher fused reduce (deterministic fixed split order) ----
    __threadfence();                      // release partials
    __syncthreads();                      // all threads' stores issued+fenced
    if (tid == 0)
        s_last = (atomicAdd(&g_cnt[mtile], 1) == NSPLIT - 1) ? 1 : 0;
    __syncthreads();
    if (!s_last) return;
    __threadfence();                      // acquire other CTAs' partials

    // 1024 float4 outputs per mtile; 256 threads x 4 each.
    // id = t + i*256: b = id>>5 (batch), o4 = id&31 (float4 col within tile)
#pragma unroll
    for (int i = 0; i < 4; ++i) {
        int id = tid + i * 256;
        int b  = id >> 5;
        int oc = row0 + (id & 31) * 4;
        size_t off = (size_t)b * OUTN + oc;
        float4 s = *reinterpret_cast<const float4*>(g_part + off);
#pragma unroll
        for (int sp = 1; sp < NSPLIT; ++sp) {
            float4 p = *reinterpret_cast<const float4*>(
                g_part + (size_t)sp * 32 * OUTN + off);
            s.x += p.x; s.y += p.y; s.z += p.z; s.w += p.w;
        }
        float4 sc = *reinterpret_cast<const float4*>(SC + oc);
        float4 bi = *reinterpret_cast<const float4*>(BI + oc);
        float4 r;
        r.x = fmaf(sc.x, s.x, bi.x);
        r.y = fmaf(sc.y, s.y, bi.y);
        r.z = fmaf(sc.z, s.z, bi.z);
        r.w = fmaf(sc.w, s.w, bi.w);
        *reinterpret_cast<float4*>(OUT + off) = r;
    }

    if (tid == 0) g_cnt[mtile] = 0;       // reset for next replay
}

extern "C" void kernel_launch(void* const* d_in, const int* in_sizes, int n_in,
                              void* d_out, int out_size) {
    (void)in_sizes; (void)n_in; (void)out_size;
    const float* x  = (const float*)d_in[0];
    const int*   wq = (const int*)d_in[1];
    const float* sc = (const float*)d_in[2];
    const float* bi = (const float*)d_in[3];
    float* out = (float*)d_out;

    lin2b_main<<<NCTA, NTHREADS>>>(x, wq, sc, bi, out);
}

// round 16
// speedup vs baseline: 1.1659x; 1.1659x over previous
#include <cuda_runtime.h>
#include <cuda_fp16.h>
#include <cstdint>
#include <cstddef>

// y[32,11008] = x[32,4096] @ (Wq * scale)^T + bias
// R16: W via ld.global.nc.L2::evict_first.v8.b32 (LDG.256: full-line reads,
// halves W wavefronts+instructions; stream-once L2 policy protects partials).
// sigma: thread cc holds k {c*64 + h*32 + cc*8 + 0..7}; steps s=2h+e use
// regs [h*8+e*4 ..+3]. x smem linear-k, XROW=576 (conflict-free LDS.128).

#define OUTN 11008
#define INK  4096
#define TM   128
#define NSPLIT 16
#define CHUNKS 4                    // 64 k each, K=256/CTA
#define NCTA (OUTN / TM * NSPLIT)   // 1376
#define NTHREADS 256
#define XROW 576                    // x smem row stride bytes (576 mod 128 = 64)

__device__ __align__(16) float g_part[NSPLIT * 32 * OUTN];   // 22.5 MB partials

__device__ __forceinline__ uint32_t tern2h(uint32_t w0, uint32_t w1) {
    uint32_t p = __byte_perm(w0, w1, 0x5410);
    uint32_t m = (p & 0x00010001u) * 0x3C00u;
    return m | (p & 0x80008000u);
}

__device__ __forceinline__ void mma16816(float d[4],
                                         uint32_t a0, uint32_t a1, uint32_t a2, uint32_t a3,
                                         uint32_t b0, uint32_t b1) {
    asm volatile(
        "mma.sync.aligned.m16n8k16.row.col.f32.f16.f16.f32 "
        "{%0,%1,%2,%3}, {%4,%5,%6,%7}, {%8,%9}, {%0,%1,%2,%3};\n"
        : "+f"(d[0]), "+f"(d[1]), "+f"(d[2]), "+f"(d[3])
        : "r"(a0), "r"(a1), "r"(a2), "r"(a3), "r"(b0), "r"(b1));
}

// 256-bit stream-once W load (L2 evict_first)
__device__ __forceinline__ void ldg8(uint32_t* r, const int* p) {
    asm volatile(
        "ld.global.nc.L2::evict_first.v8.b32 {%0,%1,%2,%3,%4,%5,%6,%7}, [%8];"
        : "=r"(r[0]), "=r"(r[1]), "=r"(r[2]), "=r"(r[3]),
          "=r"(r[4]), "=r"(r[5]), "=r"(r[6]), "=r"(r[7])
        : "l"(p));
}

// ---------------- main GEMM (per-split partial) ------------------------------
__global__ void __launch_bounds__(NTHREADS, 2)
lin2b_main(const float* __restrict__ X, const int* __restrict__ W)
{
    __shared__ __align__(16) unsigned char xsm[32 * XROW];   // 18 KB

    int tid  = threadIdx.x;
    int wid  = tid >> 5;
    int lane = tid & 31;
    int rr   = lane >> 2;
    int cc   = lane & 3;

    int mtile = blockIdx.x >> 4;
    int split = blockIdx.x & 15;
    int row0  = mtile * TM;
    int k0    = split * (CHUNKS * 64);

    // ---- prologue: x slice (32 x 256) f32 -> fp16 smem, linear k ----
    {
        int xr  = tid >> 3;
        int kb  = (tid & 7) * 32;
        const float* xs = X + (size_t)xr * INK + k0 + kb;
        unsigned char* xd = xsm + xr * XROW + kb * 2;
#pragma unroll
        for (int g = 0; g < 2; ++g) {
            uint4 st[2];
#pragma unroll
            for (int q = 0; q < 2; ++q) {
                float4 v0 = *reinterpret_cast<const float4*>(xs + g * 16 + q * 8);
                float4 v1 = *reinterpret_cast<const float4*>(xs + g * 16 + q * 8 + 4);
                __half2 p0 = __floats2half2_rn(v0.x, v0.y);
                __half2 p1 = __floats2half2_rn(v0.z, v0.w);
                __half2 p2 = __floats2half2_rn(v1.x, v1.y);
                __half2 p3 = __floats2half2_rn(v1.z, v1.w);
                st[q].x = *reinterpret_cast<uint32_t*>(&p0);
                st[q].y = *reinterpret_cast<uint32_t*>(&p1);
                st[q].z = *reinterpret_cast<uint32_t*>(&p2);
                st[q].w = *reinterpret_cast<uint32_t*>(&p3);
            }
            *reinterpret_cast<uint4*>(xd + g * 32)      = st[0];
            *reinterpret_cast<uint4*>(xd + g * 32 + 16) = st[1];
        }
    }

    // W row pointers (thread covers k ints cc*8.. within each 32-int half)
    const int* wp0 = W + (size_t)(row0 + wid * 16 + rr) * INK + k0 + cc * 8;
    const int* wp1 = wp0 + (size_t)8 * INK;

    float acc[4][4];
#pragma unroll
    for (int i = 0; i < 4; ++i)
#pragma unroll
        for (int j = 0; j < 4; ++j) acc[i][j] = 0.0f;

    // W double buffer: [buf][row(2)][16 regs]
    uint32_t wa[2][16], wb_[2][16];

    // prologue: chunk 0 -> buf 0
    ldg8(&wa[0][0], wp0);
    ldg8(&wa[0][8], wp0 + 32);
    ldg8(&wb_[0][0], wp1);
    ldg8(&wb_[0][8], wp1 + 32);
    __syncthreads();    // x smem ready; read-only afterwards

    const unsigned char* xb = xsm + rr * XROW + cc * 16;

#pragma unroll
    for (int c = 0; c < CHUNKS; ++c) {
        int cur = c & 1, nxt = cur ^ 1;
        if (c + 1 < CHUNKS) {
            ldg8(&wa[nxt][0], wp0 + (c + 1) * 64);
            ldg8(&wa[nxt][8], wp0 + (c + 1) * 64 + 32);
            ldg8(&wb_[nxt][0], wp1 + (c + 1) * 64);
            ldg8(&wb_[nxt][8], wp1 + (c + 1) * 64 + 32);
        }
#pragma unroll
        for (int g = 0; g < 2; ++g) {
            uint4 bv[4];
#pragma unroll
            for (int nf = 0; nf < 4; ++nf)
                bv[nf] = *reinterpret_cast<const uint4*>(
                    xb + nf * (8 * XROW) + c * 128 + g * 64);
#pragma unroll
            for (int e = 0; e < 2; ++e) {
                int base = g * 8 + e * 4;
                uint32_t a0 = tern2h(wa[cur][base + 0], wa[cur][base + 1]);
                uint32_t a2 = tern2h(wa[cur][base + 2], wa[cur][base + 3]);
                uint32_t a1 = tern2h(wb_[cur][base + 0], wb_[cur][base + 1]);
                uint32_t a3 = tern2h(wb_[cur][base + 2], wb_[cur][base + 3]);
#pragma unroll
                for (int nf = 0; nf < 4; ++nf)
                    mma16816(acc[nf], a0, a1, a2, a3,
                             e ? bv[nf].z : bv[nf].x,
                             e ? bv[nf].w : bv[nf].y);
            }
        }
    }

    // ---- partial epilogue ----
    int o0 = row0 + wid * 16 + rr;
    int o1 = o0 + 8;
    float* pb = g_part + (size_t)split * 32 * OUTN;
#pragma unroll
    for (int nf = 0; nf < 4; ++nf) {
        int b0 = nf * 8 + 2 * cc;
        int b1 = b0 + 1;
        pb[(size_t)b0 * OUTN + o0] = acc[nf][0];
        pb[(size_t)b1 * OUTN + o0] = acc[nf][1];
        pb[(size_t)b0 * OUTN + o1] = acc[nf][2];
        pb[(size_t)b1 * OUTN + o1] = acc[nf][3];
    }
}

// ---------------- reduce: out = bias + scale * sum(parts) --------------------
__global__ void __launch_bounds__(256)
reduce_k(const float* __restrict__ SC, const float* __restrict__ BI,
         float* __restrict__ OUT)
{
    int t = blockIdx.x * blockDim.x + threadIdx.x;
    if (t >= 32 * OUTN / 4) return;
    size_t idx = (size_t)t * 4;
    int o = (int)(idx % OUTN);

    float4 s = *reinterpret_cast<const float4*>(g_part + idx);
#pragma unroll
    for (int sp = 1; sp < NSPLIT; ++sp) {
        float4 p = *reinterpret_cast<const float4*>(g_part + (size_t)sp * 32 * OUTN + idx);
        s.x += p.x; s.y += p.y; s.z += p.z; s.w += p.w;
    }
    float4 sc = *reinterpret_cast<const float4*>(SC + o);
    float4 bi = *reinterpret_cast<const float4*>(BI + o);
    float4 r;
    r.x = fmaf(sc.x, s.x, bi.x);
    r.y = fmaf(sc.y, s.y, bi.y);
    r.z = fmaf(sc.z, s.z, bi.z);
    r.w = fmaf(sc.w, s.w, bi.w);
    *reinterpret_cast<float4*>(OUT + idx) = r;
}

extern "C" void kernel_launch(void* const* d_in, const int* in_sizes, int n_in,
                              void* d_out, int out_size) {
    (void)in_sizes; (void)n_in; (void)out_size;
    const float* x  = (const float*)d_in[0];
    const int*   wq = (const int*)d_in[1];
    const float* sc = (const float*)d_in[2];
    const float* bi = (const float*)d_in[3];
    float* out = (float*)d_out;

    lin2b_main<<<NCTA, NTHREADS>>>(x, wq);
    reduce_k<<<(32 * OUTN / 4 + 255) / 256, 256>>>(sc, bi, out);
}

// round 17
// speedup vs baseline: 1.2371x; 1.0610x over previous
#include <cuda_runtime.h>
#include <cuda_fp16.h>
#include <cstdint>
#include <cstddef>

// y[32,11008] = x[32,4096] @ (Wq * scale)^T + bias
// R17 = R16 main (LDG.256 evict_first W, barrier-free fp16 HMMA, NSPLIT=16)
// + fp16 partials packed as half2(b,b+1) in [split*16+bpair][OUTN] layout:
// halves partial round-trip (22.5 -> 11.25 MB), coalesced reduce loads,
// 16-deep MLP reduce. Deterministic fixed-order sum.

#define OUTN 11008
#define INK  4096
#define TM   128
#define NSPLIT 16
#define CHUNKS 4                    // 64 k each, K=256/CTA
#define NCTA (OUTN / TM * NSPLIT)   // 1376
#define NTHREADS 256
#define XROW 576                    // x smem row stride bytes

__device__ __align__(16) uint32_t g_ph[NSPLIT * 16 * OUTN];  // 11.25 MB half2 partials

__device__ __forceinline__ uint32_t tern2h(uint32_t w0, uint32_t w1) {
    uint32_t p = __byte_perm(w0, w1, 0x5410);
    uint32_t m = (p & 0x00010001u) * 0x3C00u;
    return m | (p & 0x80008000u);
}

__device__ __forceinline__ void mma16816(float d[4],
                                         uint32_t a0, uint32_t a1, uint32_t a2, uint32_t a3,
                                         uint32_t b0, uint32_t b1) {
    asm volatile(
        "mma.sync.aligned.m16n8k16.row.col.f32.f16.f16.f32 "
        "{%0,%1,%2,%3}, {%4,%5,%6,%7}, {%8,%9}, {%0,%1,%2,%3};\n"
        : "+f"(d[0]), "+f"(d[1]), "+f"(d[2]), "+f"(d[3])
        : "r"(a0), "r"(a1), "r"(a2), "r"(a3), "r"(b0), "r"(b1));
}

// 256-bit stream-once W load (L2 evict_first)
__device__ __forceinline__ void ldg8(uint32_t* r, const int* p) {
    asm volatile(
        "ld.global.nc.L2::evict_first.v8.b32 {%0,%1,%2,%3,%4,%5,%6,%7}, [%8];"
        : "=r"(r[0]), "=r"(r[1]), "=r"(r[2]), "=r"(r[3]),
          "=r"(r[4]), "=r"(r[5]), "=r"(r[6]), "=r"(r[7])
        : "l"(p));
}

// ---------------- main GEMM (per-split fp16 partials) ------------------------
__global__ void __launch_bounds__(NTHREADS, 2)
lin2b_main(const float* __restrict__ X, const int* __restrict__ W)
{
    __shared__ __align__(16) unsigned char xsm[32 * XROW];   // 18 KB

    int tid  = threadIdx.x;
    int wid  = tid >> 5;
    int lane = tid & 31;
    int rr   = lane >> 2;
    int cc   = lane & 3;

    int mtile = blockIdx.x >> 4;
    int split = blockIdx.x & 15;
    int row0  = mtile * TM;
    int k0    = split * (CHUNKS * 64);

    // ---- prologue: x slice (32 x 256) f32 -> fp16 smem, linear k ----
    {
        int xr  = tid >> 3;
        int kb  = (tid & 7) * 32;
        const float* xs = X + (size_t)xr * INK + k0 + kb;
        unsigned char* xd = xsm + xr * XROW + kb * 2;
#pragma unroll
        for (int g = 0; g < 2; ++g) {
            uint4 st[2];
#pragma unroll
            for (int q = 0; q < 2; ++q) {
                float4 v0 = *reinterpret_cast<const float4*>(xs + g * 16 + q * 8);
                float4 v1 = *reinterpret_cast<const float4*>(xs + g * 16 + q * 8 + 4);
                __half2 p0 = __floats2half2_rn(v0.x, v0.y);
                __half2 p1 = __floats2half2_rn(v0.z, v0.w);
                __half2 p2 = __floats2half2_rn(v1.x, v1.y);
                __half2 p3 = __floats2half2_rn(v1.z, v1.w);
                st[q].x = *reinterpret_cast<uint32_t*>(&p0);
                st[q].y = *reinterpret_cast<uint32_t*>(&p1);
                st[q].z = *reinterpret_cast<uint32_t*>(&p2);
                st[q].w = *reinterpret_cast<uint32_t*>(&p3);
            }
            *reinterpret_cast<uint4*>(xd + g * 32)      = st[0];
            *reinterpret_cast<uint4*>(xd + g * 32 + 16) = st[1];
        }
    }

    const int* wp0 = W + (size_t)(row0 + wid * 16 + rr) * INK + k0 + cc * 8;
    const int* wp1 = wp0 + (size_t)8 * INK;

    float acc[4][4];
#pragma unroll
    for (int i = 0; i < 4; ++i)
#pragma unroll
        for (int j = 0; j < 4; ++j) acc[i][j] = 0.0f;

    uint32_t wa[2][16], wb_[2][16];

    ldg8(&wa[0][0], wp0);
    ldg8(&wa[0][8], wp0 + 32);
    ldg8(&wb_[0][0], wp1);
    ldg8(&wb_[0][8], wp1 + 32);
    __syncthreads();    // x smem ready; read-only afterwards

    const unsigned char* xb = xsm + rr * XROW + cc * 16;

#pragma unroll
    for (int c = 0; c < CHUNKS; ++c) {
        int cur = c & 1, nxt = cur ^ 1;
        if (c + 1 < CHUNKS) {
            ldg8(&wa[nxt][0], wp0 + (c + 1) * 64);
            ldg8(&wa[nxt][8], wp0 + (c + 1) * 64 + 32);
            ldg8(&wb_[nxt][0], wp1 + (c + 1) * 64);
            ldg8(&wb_[nxt][8], wp1 + (c + 1) * 64 + 32);
        }
#pragma unroll
        for (int g = 0; g < 2; ++g) {
            uint4 bv[4];
#pragma unroll
            for (int nf = 0; nf < 4; ++nf)
                bv[nf] = *reinterpret_cast<const uint4*>(
                    xb + nf * (8 * XROW) + c * 128 + g * 64);
#pragma unroll
            for (int e = 0; e < 2; ++e) {
                int base = g * 8 + e * 4;
                uint32_t a0 = tern2h(wa[cur][base + 0], wa[cur][base + 1]);
                uint32_t a2 = tern2h(wa[cur][base + 2], wa[cur][base + 3]);
                uint32_t a1 = tern2h(wb_[cur][base + 0], wb_[cur][base + 1]);
                uint32_t a3 = tern2h(wb_[cur][base + 2], wb_[cur][base + 3]);
#pragma unroll
                for (int nf = 0; nf < 4; ++nf)
                    mma16816(acc[nf], a0, a1, a2, a3,
                             e ? bv[nf].z : bv[nf].x,
                             e ? bv[nf].w : bv[nf].y);
            }
        }
    }

    // ---- fp16 partial epilogue: half2(b0,b1) at [split*16+bpair][o] ----
    int o0 = row0 + wid * 16 + rr;
    int o1 = o0 + 8;
#pragma unroll
    for (int nf = 0; nf < 4; ++nf) {
        int bp = nf * 4 + cc;                       // b-pair index (b0=2*bp)
        uint32_t base = (uint32_t)(split * 16 + bp) * OUTN;
        __half2 v0 = __floats2half2_rn(acc[nf][0], acc[nf][1]);   // (b0,b1)@o0
        __half2 v1 = __floats2half2_rn(acc[nf][2], acc[nf][3]);   // (b0,b1)@o1
        g_ph[base + o0] = *reinterpret_cast<uint32_t*>(&v0);
        g_ph[base + o1] = *reinterpret_cast<uint32_t*>(&v1);
    }
}

// ---------------- reduce: out = bias + scale * sum(parts) --------------------
// one thread per (bpair, o): 16 independent 4B loads, coalesced in o.
__global__ void __launch_bounds__(256)
reduce_k(const float* __restrict__ SC, const float* __restrict__ BI,
         float* __restrict__ OUT)
{
    int t = blockIdx.x * blockDim.x + threadIdx.x;
    if (t >= 16 * OUTN) return;
    int bp = t / OUTN;
    int o  = t - bp * OUTN;

    float s0 = 0.0f, s1 = 0.0f;
#pragma unroll
    for (int sp = 0; sp < NSPLIT; ++sp) {
        uint32_t v = g_ph[(uint32_t)(sp * 16 + bp) * OUTN + o];
        __half2 h = *reinterpret_cast<__half2*>(&v);
        s0 += __low2float(h);
        s1 += __high2float(h);
    }
    float sc = SC[o], bi = BI[o];
    int b0 = 2 * bp;
    OUT[(size_t)b0 * OUTN + o]       = fmaf(sc, s0, bi);
    OUT[(size_t)(b0 + 1) * OUTN + o] = fmaf(sc, s1, bi);
}

extern "C" void kernel_launch(void* const* d_in, const int* in_sizes, int n_in,
                              void* d_out, int out_size) {
    (void)in_sizes; (void)n_in; (void)out_size;
    const float* x  = (const float*)d_in[0];
    const int*   wq = (const int*)d_in[1];
    const float* sc = (const float*)d_in[2];
    const float* bi = (const float*)d_in[3];
    float* out = (float*)d_out;

    lin2b_main<<<NCTA, NTHREADS>>>(x, wq);
    reduce_k<<<(16 * OUTN + 255) / 256, 256>>>(sc, bi, out);
}